// round 1
// baseline (speedup 1.0000x reference)
#include <cuda_runtime.h>

// Hamilton product of quaternions packed in the last dim (w, x, y, z).
// Shapes: q1, q2: (32, 4096, 64, 4) fp32 -> 8,388,608 quaternions.
// Pure streaming op: float4 per quaternion, 1 thread per quaternion.

__global__ void __launch_bounds__(256) hamilton_kernel(
    const float4* __restrict__ q1,
    const float4* __restrict__ q2,
    float4* __restrict__ out,
    int n_quat)
{
    int i = blockIdx.x * blockDim.x + threadIdx.x;
    if (i >= n_quat) return;

    float4 a = q1[i];
    float4 b = q2[i];

    // a = (w1, x1, y1, z1), b = (w2, x2, y2, z2)
    float4 r;
    r.x = a.x * b.x - a.y * b.y - a.z * b.z - a.w * b.w;  // w
    r.y = a.x * b.y + a.y * b.x + a.z * b.w - a.w * b.z;  // x
    r.z = a.x * b.z - a.y * b.w + a.z * b.x + a.w * b.y;  // y
    r.w = a.x * b.w + a.y * b.z - a.z * b.y + a.w * b.x;  // z

    out[i] = r;
}

extern "C" void kernel_launch(void* const* d_in, const int* in_sizes, int n_in,
                              void* d_out, int out_size) {
    const float4* q1 = (const float4*)d_in[0];
    const float4* q2 = (const float4*)d_in[1];
    float4* out = (float4*)d_out;

    int n_quat = in_sizes[0] / 4;  // 33,554,432 / 4 = 8,388,608

    int threads = 256;
    int blocks = (n_quat + threads - 1) / threads;
    hamilton_kernel<<<blocks, threads>>>(q1, q2, out, n_quat);
}